// round 13
// baseline (speedup 1.0000x reference)
#include <cuda_runtime.h>
#include <cuda_bf16.h>
#include <math.h>
#include <stdint.h>

#define S_LEN   4096
#define DMODEL  768
#define NHEADS  12
#define DHEAD   64

#define PERM8(c) ((((c) & 3) << 1) | ((c) >> 2))

// ---------------- scratch (no allocations allowed) ----------------
__device__ float g_qh[NHEADS * S_LEN * DHEAD];   // [h][s][d']  tf32+perm
__device__ float g_kh[NHEADS * S_LEN * DHEAD];   // [h][s][d']  tf32+perm
__device__ float g_vh[NHEADS * S_LEN * DHEAD];   // [h][s][d]   tf32 plain
__device__ float g_att[S_LEN * DMODEL];          // [s][h*64+d] fp32 plain

// ---------------- helpers ----------------
__device__ __forceinline__ unsigned f2tf32(float x) {
    unsigned r;
    asm("cvt.rna.tf32.f32 %0, %1;" : "=r"(r) : "f"(x));
    return r;
}
__device__ __forceinline__ float tf32f(float x) {
    return __uint_as_float(f2tf32(x));
}

__device__ __forceinline__ void cp_async16(void* smem, const void* g) {
    unsigned s = (unsigned)__cvta_generic_to_shared(smem);
    asm volatile("cp.async.cg.shared.global [%0], [%1], 16;" :: "r"(s), "l"(g));
}
__device__ __forceinline__ void cp_commit() {
    asm volatile("cp.async.commit_group;");
}
template<int N> __device__ __forceinline__ void cp_wait() {
    asm volatile("cp.async.wait_group %0;" :: "n"(N));
}

#define MBAR_INIT(mbar, cnt) \
    asm volatile("mbarrier.init.shared.b64 [%0], %1;" :: "r"(mbar), "r"(cnt) : "memory")
#define MBAR_ARRIVE(mbar) \
    asm volatile("mbarrier.arrive.shared.b64 _, [%0];" :: "r"(mbar) : "memory")
#define CPASYNC_MBAR_ARRIVE(mbar) \
    asm volatile("cp.async.mbarrier.arrive.noinc.shared.b64 [%0];" :: "r"(mbar) : "memory")

__device__ __forceinline__ void mbar_wait(uint32_t mbar, uint32_t parity) {
    asm volatile(
        "{\n\t.reg .pred P;\n\t"
        "WL%=:\n\t"
        "mbarrier.try_wait.parity.acquire.cta.shared::cta.b64 P, [%0], %1, 0x989680;\n\t"
        "@P bra WD%=;\n\t"
        "bra WL%=;\n\t"
        "WD%=:\n\t}"
        :: "r"(mbar), "r"(parity) : "memory");
}

// D += A(16x8) * B(8x8), tf32 inputs, fp32 accum.
__device__ __forceinline__ void mma_tf32(float* c, unsigned a0, unsigned a1,
                                         unsigned a2, unsigned a3,
                                         unsigned b0, unsigned b1) {
    asm("mma.sync.aligned.m16n8k8.row.col.f32.tf32.tf32.f32 "
        "{%0,%1,%2,%3}, {%4,%5,%6,%7}, {%8,%9}, {%0,%1,%2,%3};"
        : "+f"(c[0]), "+f"(c[1]), "+f"(c[2]), "+f"(c[3])
        : "r"(a0), "r"(a1), "r"(a2), "r"(a3), "r"(b0), "r"(b1));
}

// =================================================================
// tf32 GEMM, cp.async 2-stage pipeline, raw fp32 inputs, CVT at
// fragment load (proven). C = A*W^T + bias. M=4096, N=K=768.
// modes: 0 = plain fp32 out; 1 = [h][s][d'] tf32+perm (Q,K);
//        3 = [h][s][d] tf32 plain (V).
// =================================================================
#define GSTR 36
#define GEMM_STAGE (128 * GSTR)
#define GEMM_SMEM  (2 * 2 * GEMM_STAGE * 4)      // 73728 bytes

struct GemmPtrs { const float* A; const float* W; const float* bias; float* C; int mode; };
struct GemmArgs3 { GemmPtrs p[3]; };

__global__ __launch_bounds__(256, 2)
void gemm_tf32_kernel(GemmArgs3 args)
{
    extern __shared__ float gsm[];
    const GemmPtrs gp = args.p[blockIdx.z];
    const float* __restrict__ A    = gp.A;
    const float* __restrict__ W    = gp.W;
    const float* __restrict__ bias = gp.bias;
    float* __restrict__ C          = gp.C;
    const int mode = gp.mode;

    const int tid  = threadIdx.x;
    const int warp = tid >> 5;
    const int lane = tid & 31;
    const int gid  = lane >> 2;
    const int tig  = lane & 3;

    const int m0 = blockIdx.y * 128;
    const int n0 = blockIdx.x * 128;
    const int wm = (warp >> 2) * 64;
    const int wn = (warp & 3) * 32;

    const int cr  = tid >> 3;
    const int ccc = (tid & 7) << 2;

    float acc[4][4][4];
#pragma unroll
    for (int mi = 0; mi < 4; ++mi)
#pragma unroll
        for (int ni = 0; ni < 4; ++ni)
#pragma unroll
            for (int f = 0; f < 4; ++f) acc[mi][ni][f] = 0.f;

    auto issue = [&](int kt, int st) {
        float* As = gsm + st * 2 * GEMM_STAGE;
        float* Ws = As + GEMM_STAGE;
        const int k0 = kt * 32;
#pragma unroll
        for (int i = 0; i < 4; ++i) {
            const int r = cr + i * 32;
            cp_async16(As + r * GSTR + ccc, A + (size_t)(m0 + r) * DMODEL + k0 + ccc);
            cp_async16(Ws + r * GSTR + ccc, W + (size_t)(n0 + r) * DMODEL + k0 + ccc);
        }
        cp_commit();
    };

    issue(0, 0);

    const int NKT = DMODEL / 32;   // 24
    for (int kt = 0; kt < NKT; ++kt) {
        const int buf = kt & 1;
        if (kt + 1 < NKT) { issue(kt + 1, buf ^ 1); cp_wait<1>(); }
        else              { cp_wait<0>(); }
        __syncthreads();

        const float* As = gsm + buf * 2 * GEMM_STAGE;
        const float* Ws = As + GEMM_STAGE;

#pragma unroll
        for (int kk = 0; kk < 4; ++kk) {
            const int k4 = kk * 8;
            unsigned a[4][4], b[4][2];
#pragma unroll
            for (int mi = 0; mi < 4; ++mi) {
                const int r = wm + mi * 16 + gid;
                a[mi][0] = f2tf32(As[r * GSTR + k4 + tig]);
                a[mi][1] = f2tf32(As[(r + 8) * GSTR + k4 + tig]);
                a[mi][2] = f2tf32(As[r * GSTR + k4 + tig + 4]);
                a[mi][3] = f2tf32(As[(r + 8) * GSTR + k4 + tig + 4]);
            }
#pragma unroll
            for (int ni = 0; ni < 4; ++ni) {
                const int n = wn + ni * 8 + gid;
                b[ni][0] = f2tf32(Ws[n * GSTR + k4 + tig]);
                b[ni][1] = f2tf32(Ws[n * GSTR + k4 + tig + 4]);
            }
#pragma unroll
            for (int mi = 0; mi < 4; ++mi)
#pragma unroll
                for (int ni = 0; ni < 4; ++ni)
                    mma_tf32(acc[mi][ni], a[mi][0], a[mi][1], a[mi][2], a[mi][3],
                             b[ni][0], b[ni][1]);
        }
        __syncthreads();
    }

    // epilogue
    const int pt2 = PERM8(2 * tig);
#pragma unroll
    for (int mi = 0; mi < 4; ++mi) {
#pragma unroll
        for (int ni = 0; ni < 4; ++ni) {
            const int n = n0 + wn + ni * 8 + 2 * tig;
            const float b0 = bias[n], b1 = bias[n + 1];
#pragma unroll
            for (int half = 0; half < 2; ++half) {
                const int m = m0 + wm + mi * 16 + gid + half * 8;
                const float v0 = acc[mi][ni][half * 2 + 0] + b0;
                const float v1 = acc[mi][ni][half * 2 + 1] + b1;
                if (mode == 0) {
                    float* dst = C + (size_t)m * DMODEL + n;
                    dst[0] = v0; dst[1] = v1;
                } else if (mode == 1) {
                    const int bse = (n & 63) & ~7;
                    float* dst = C + (size_t)(n >> 6) * (S_LEN * DHEAD)
                                   + (size_t)m * DHEAD + bse;
                    dst[pt2]     = tf32f(v0);
                    dst[pt2 + 2] = tf32f(v1);
                } else {
                    float* dst = C + (size_t)(n >> 6) * (S_LEN * DHEAD)
                                   + (size_t)m * DHEAD + (n & 63);
                    dst[0] = tf32f(v0); dst[1] = tf32f(v1);
                }
            }
        }
    }
}

// =================================================================
// Flash attention (causal), tf32 mma.sync, fixed-shift softmax,
// SOFTWARE-PIPELINED mainloop:
//     softmax(t) -> [wait + QK(t+1) into same sc regs] -> PV(t)
// QK(t+1) is independent of softmax(t), hiding exp2/STS latency
// behind tensor issues; PV(t) reads P long after its stores.
// BR=64: 4 compute warps (m16) + 1 producer = 160 threads.
// BC=32, 3-stage K/V ring, no __syncthreads in mainloop.
// CTA i processes q-tiles {63-i, i}: constant 130 tiles per CTA.
// =================================================================
#define FBC    32
#define KSTR   68
#define PSTR   36
#define NSTAGE 3
#define STG_WORDS (2 * FBC * KSTR)                          // 4352 words
#define FL_BAR_OFF ((NSTAGE * STG_WORDS + 64 * PSTR) * 4)   // 61440
#define FLASH_SMEM (FL_BAR_OFF + 16 * NSTAGE)

__global__ __launch_bounds__(160, 3)
void flash_tf32_kernel(const float* __restrict__ Q,
                       const float* __restrict__ K,
                       const float* __restrict__ V,
                       float* __restrict__ O)
{
    extern __shared__ float fsm[];
    float* stages = fsm;                                   // [3][4352]
    unsigned* Ps = (unsigned*)(fsm + NSTAGE * STG_WORDS);  // 64 x 36

    uint32_t sbase;
    asm("{ .reg .u64 t; cvta.to.shared.u64 t, %1; cvt.u32.u64 %0, t; }"
        : "=r"(sbase) : "l"(fsm));
    const uint32_t FULLB  = sbase + FL_BAR_OFF;
    const uint32_t EMPTYB = sbase + FL_BAR_OFF + 8 * NSTAGE;

    const int tid  = threadIdx.x;
    const int warp = tid >> 5;      // 0..3 compute, 4 producer
    const int lane = tid & 31;
    const int gid  = lane >> 2;
    const int tig  = lane & 3;

    const int pairIdx = blockIdx.x;     // 0..31
    const int h       = blockIdx.y;

    const float* Qh = Q + (size_t)h * S_LEN * DHEAD;
    const float* Kh = K + (size_t)h * S_LEN * DHEAD;
    const float* Vh = V + (size_t)h * S_LEN * DHEAD;

    if (tid == 0) {
#pragma unroll
        for (int s = 0; s < NSTAGE; ++s) {
            MBAR_INIT(FULLB + 8 * s, 32);   // cp.async per-lane arrivals
            MBAR_INIT(EMPTYB + 8 * s, 4);   // one arrive per compute warp
        }
    }
    __syncthreads();

    const float SCL   = 0.125f * 1.44269504f;
    const float SHIFT = -16.0f;

    if (warp == 4) {
        // ---------------- producer warp ----------------
        int s = 0;
        unsigned eph = 0;
        int n = 0;
#pragma unroll 1
        for (int pass = 0; pass < 2; ++pass) {
            const int qt = (pass == 0) ? (63 - pairIdx) : pairIdx;
            const int nT = 2 * (qt + 1);
#pragma unroll 1
            for (int t = 0; t < nT; ++t) {
                if (n >= NSTAGE) {
                    mbar_wait(EMPTYB + 8 * s, (eph >> s) & 1);
                    eph ^= 1u << s;
                }
                float* Ks = stages + s * STG_WORDS;
                float* Vs = Ks + FBC * KSTR;
                const int j0 = t * FBC;
                const float* ksrc = Kh + (size_t)(j0 + lane) * DHEAD;
                const float* vsrc = Vh + (size_t)(j0 + lane) * DHEAD;
                float* kdst = Ks + lane * KSTR;
                float* vdst = Vs + lane * KSTR;
#pragma unroll
                for (int c = 0; c < 16; ++c) {
                    cp_async16(kdst + c * 4, ksrc + c * 4);
                    cp_async16(vdst + c * 4, vsrc + c * 4);
                }
                CPASYNC_MBAR_ARRIVE(FULLB + 8 * s);
                if (++s == NSTAGE) s = 0;
                ++n;
            }
        }
        cp_wait<0>();
        return;
    }

    // ---------------- compute warps (m16 each) ----------------
    const int w16 = warp * 16;
    const int r0  = w16 + gid;          // Ps row (0..63)
    const int pos0 = PERM8(2 * tig);

    int s = 0;                          // next stage index to consume
    unsigned fph = 0;

#pragma unroll 1
    for (int pass = 0; pass < 2; ++pass) {
        const int qt = (pass == 0) ? (63 - pairIdx) : pairIdx;
        const int m0 = qt * 64;
        const int nT = 2 * (qt + 1);

        // Q fragments (tf32+perm in gmem)
        unsigned qa[8][4];
        {
            const int rr = m0 + w16 + gid;
#pragma unroll
            for (int kk = 0; kk < 8; ++kk) {
                const int c = kk * 8 + 2 * tig;
                uint2 t0 = *(const uint2*)(Qh + (size_t)rr * DHEAD + c);
                uint2 t1 = *(const uint2*)(Qh + (size_t)(rr + 8) * DHEAD + c);
                qa[kk][0] = t0.x; qa[kk][1] = t1.x;
                qa[kk][2] = t0.y; qa[kk][3] = t1.y;
            }
        }

        float o[8][4];
#pragma unroll
        for (int ni = 0; ni < 8; ++ni)
#pragma unroll
            for (int f = 0; f < 4; ++f) o[ni][f] = 0.f;
        float lp0 = 0.f, lp1 = 0.f;     // per-thread denominator partials

        float sc[4][4];                 // raw scores of the "current" tile

        // ---- prologue: QK for tile 0 of this pass ----
        mbar_wait(FULLB + 8 * s, (fph >> s) & 1);
        fph ^= 1u << s;
        {
            const unsigned* Ks = (const unsigned*)(stages + s * STG_WORDS);
#pragma unroll
            for (int ni = 0; ni < 4; ++ni)
#pragma unroll
                for (int f = 0; f < 4; ++f) sc[ni][f] = 0.f;
#pragma unroll
            for (int kk = 0; kk < 8; ++kk) {
                const int kb = kk * 8 + 2 * tig;
#pragma unroll
                for (int ni = 0; ni < 4; ++ni) {
                    const int n = ni * 8 + gid;
                    uint2 bb = *(const uint2*)(Ks + n * KSTR + kb);
                    mma_tf32(sc[ni], qa[kk][0], qa[kk][1], qa[kk][2], qa[kk][3],
                             bb.x, bb.y);
                }
            }
        }
        int s_cur = s;                      // stage holding tile t's V
        s = (s + 1 == NSTAGE) ? 0 : s + 1;

#pragma unroll 1
        for (int t = 0; t < nT; ++t) {
            const int j0 = t * FBC;
            const bool masked = (t >= 2 * qt);

            // ---- fixed-shift scale + causal mask (tile t) ----
            if (masked) {
                const int q0 = m0 + w16 + gid;
                const int q1 = q0 + 8;
#pragma unroll
                for (int ni = 0; ni < 4; ++ni) {
                    const int kc0 = j0 + ni * 8 + 2 * tig;
                    const int kc1 = kc0 + 1;
                    sc[ni][0] = (kc0 <= q0) ? fmaf(sc[ni][0], SCL, SHIFT) : -1e30f;
                    sc[ni][1] = (kc1 <= q0) ? fmaf(sc[ni][1], SCL, SHIFT) : -1e30f;
                    sc[ni][2] = (kc0 <= q1) ? fmaf(sc[ni][2], SCL, SHIFT) : -1e30f;
                    sc[ni][3] = (kc1 <= q1) ? fmaf(sc[ni][3], SCL, SHIFT) : -1e30f;
                }
            } else {
#pragma unroll
                for (int ni = 0; ni < 4; ++ni)
#pragma unroll
                    for (int f = 0; f < 4; ++f)
                        sc[ni][f] = fmaf(sc[ni][f], SCL, SHIFT);
            }

            // ---- p = exp2(s), store P, accumulate denominator ----
#pragma unroll
            for (int ni = 0; ni < 4; ++ni) {
                const float p0 = exp2f(sc[ni][0]);
                const float p1 = exp2f(sc[ni][1]);
                const float p2 = exp2f(sc[ni][2]);
                const float p3 = exp2f(sc[ni][3]);
                lp0 += p0 + p1; lp1 += p2 + p3;
                const int cb = ni * 8 + pos0;
                Ps[r0 * PSTR + cb]           = f2tf32(p0);
                Ps[r0 * PSTR + cb + 2]       = f2tf32(p1);
                Ps[(r0 + 8) * PSTR + cb]     = f2tf32(p2);
                Ps[(r0 + 8) * PSTR + cb + 2] = f2tf32(p3);
            }

            // ---- prefetch: QK(t+1) into sc (independent of softmax) ----
            int s_nxt = s_cur;
            if (t + 1 < nT) {
                mbar_wait(FULLB + 8 * s, (fph >> s) & 1);
                fph ^= 1u << s;
                const unsigned* Ksn = (const unsigned*)(stages + s * STG_WORDS);
                float scn[4][4];
#pragma unroll
                for (int ni = 0; ni < 4; ++ni)
#pragma unroll
                    for (int f = 0; f < 4; ++f) scn[ni][f] = 0.f;
#pragma unroll
                for (int kk = 0; kk < 8; ++kk) {
                    const int kb = kk * 8 + 2 * tig;
#pragma unroll
                    for (int ni = 0; ni < 4; ++ni) {
                        const int n = ni * 8 + gid;
                        uint2 bb = *(const uint2*)(Ksn + n * KSTR + kb);
                        mma_tf32(scn[ni], qa[kk][0], qa[kk][1], qa[kk][2], qa[kk][3],
                                 bb.x, bb.y);
                    }
                }
#pragma unroll
                for (int ni = 0; ni < 4; ++ni)
#pragma unroll
                    for (int f = 0; f < 4; ++f) sc[ni][f] = scn[ni][f];
                s_nxt = s;
                s = (s + 1 == NSTAGE) ? 0 : s + 1;
            }

            __syncwarp();   // P stores visible to all lanes of this warp

            // ---- O += P V  (tile t, k = 32 keys) ----
            {
                const unsigned* Vs = (const unsigned*)(stages + s_cur * STG_WORDS)
                                   + FBC * KSTR;
#pragma unroll
                for (int kk = 0; kk < 4; ++kk) {
                    const int kb = kk * 8 + 2 * tig;
                    uint2 alo = *(const uint2*)(Ps + r0 * PSTR + kb);
                    uint2 ahi = *(const uint2*)(Ps + (r0 + 8) * PSTR + kb);
#pragma unroll
                    for (int ni = 0; ni < 8; ++ni) {
                        const int n = ni * 8 + gid;
                        unsigned b0 = Vs[(kk * 8 + tig) * KSTR + n];
                        unsigned b1 = Vs[(kk * 8 + tig + 4) * KSTR + n];
                        mma_tf32(o[ni], alo.x, ahi.x, alo.y, ahi.y, b0, b1);
                    }
                }
            }

            __syncwarp();   // P reads done before next tile overwrites
            if (lane == 0) MBAR_ARRIVE(EMPTYB + 8 * s_cur);
            s_cur = s_nxt;
        }

        // ---- single denominator reduction per pass ----
#pragma unroll
        for (int off = 1; off <= 2; off <<= 1) {
            lp0 += __shfl_xor_sync(0xffffffffu, lp0, off);
            lp1 += __shfl_xor_sync(0xffffffffu, lp1, off);
        }
        const float inv0 = 1.f / lp0;
        const float inv1 = 1.f / lp1;

        // epilogue: normalize + write plain fp32 [s][h*64+d]
        const int rr = m0 + w16 + gid;
#pragma unroll
        for (int ni = 0; ni < 8; ++ni) {
            const int c = h * DHEAD + ni * 8 + 2 * tig;
            float* d0 = O + (size_t)rr * DMODEL + c;
            float* d1 = O + (size_t)(rr + 8) * DMODEL + c;
            d0[0] = o[ni][0] * inv0; d0[1] = o[ni][1] * inv0;
            d1[0] = o[ni][2] * inv1; d1[1] = o[ni][3] * inv1;
        }
    }
}

// =================================================================
extern "C" void kernel_launch(void* const* d_in, const int* in_sizes, int n_in,
                              void* d_out, int out_size)
{
    const float* q  = (const float*)d_in[0];
    const float* k  = (const float*)d_in[1];
    const float* v  = (const float*)d_in[2];
    const float* wq = (const float*)d_in[3];
    const float* bq = (const float*)d_in[4];
    const float* wk = (const float*)d_in[5];
    const float* bk = (const float*)d_in[6];
    const float* wv = (const float*)d_in[7];
    const float* bv = (const float*)d_in[8];
    const float* wo = (const float*)d_in[9];
    const float* bo = (const float*)d_in[10];
    float* out = (float*)d_out;

    void *pq, *pk, *pv, *patt;
    cudaGetSymbolAddress(&pq,  g_qh);
    cudaGetSymbolAddress(&pk,  g_kh);
    cudaGetSymbolAddress(&pv,  g_vh);
    cudaGetSymbolAddress(&patt, g_att);

    static bool attr_done = false;
    if (!attr_done) {
        cudaFuncSetAttribute(gemm_tf32_kernel,
                             cudaFuncAttributeMaxDynamicSharedMemorySize, GEMM_SMEM);
        cudaFuncSetAttribute(flash_tf32_kernel,
                             cudaFuncAttributeMaxDynamicSharedMemorySize, FLASH_SMEM);
        attr_done = true;
    }

    // 1) fused Q/K/V projections (raw fp32 inputs, CVT at fragment load)
    GemmArgs3 qkv;
    qkv.p[0] = { q, wq, bq, (float*)pq, 1 };
    qkv.p[1] = { k, wk, bk, (float*)pk, 1 };
    qkv.p[2] = { v, wv, bv, (float*)pv, 3 };
    gemm_tf32_kernel<<<dim3(DMODEL / 128, S_LEN / 128, 3), 256, GEMM_SMEM>>>(qkv);

    // 2) flash attention (paired q-tiles, pipelined mainloop)
    flash_tf32_kernel<<<dim3(32, NHEADS), 160, FLASH_SMEM>>>(
        (const float*)pq, (const float*)pk, (const float*)pv, (float*)patt);

    // 3) output projection (raw fp32 g_att, CVT at fragment load)
    GemmArgs3 oproj;
    oproj.p[0] = { (const float*)patt, wo, bo, out, 0 };
    oproj.p[1] = oproj.p[0];
    oproj.p[2] = oproj.p[0];
    gemm_tf32_kernel<<<dim3(DMODEL / 128, S_LEN / 128, 1), 256, GEMM_SMEM>>>(oproj);
}

// round 14
// speedup vs baseline: 1.0261x; 1.0261x over previous
#include <cuda_runtime.h>
#include <cuda_bf16.h>
#include <math.h>
#include <stdint.h>

#define S_LEN   4096
#define DMODEL  768
#define NHEADS  12
#define DHEAD   64

#define PERM8(c) ((((c) & 3) << 1) | ((c) >> 2))

// ---------------- scratch (no allocations allowed) ----------------
__device__ float g_qh[NHEADS * S_LEN * DHEAD];   // [h][s][d']  tf32+perm
__device__ float g_kh[NHEADS * S_LEN * DHEAD];   // [h][s][d']  tf32+perm
__device__ float g_vh[NHEADS * S_LEN * DHEAD];   // [h][s][d]   tf32 plain
__device__ float g_att[S_LEN * DMODEL];          // [s][h*64+d] fp32 plain

// ---------------- helpers ----------------
__device__ __forceinline__ unsigned f2tf32(float x) {
    unsigned r;
    asm("cvt.rna.tf32.f32 %0, %1;" : "=r"(r) : "f"(x));
    return r;
}
__device__ __forceinline__ float tf32f(float x) {
    return __uint_as_float(f2tf32(x));
}

__device__ __forceinline__ void cp_async16(void* smem, const void* g) {
    unsigned s = (unsigned)__cvta_generic_to_shared(smem);
    asm volatile("cp.async.cg.shared.global [%0], [%1], 16;" :: "r"(s), "l"(g));
}
__device__ __forceinline__ void cp_commit() {
    asm volatile("cp.async.commit_group;");
}
template<int N> __device__ __forceinline__ void cp_wait() {
    asm volatile("cp.async.wait_group %0;" :: "n"(N));
}

#define MBAR_INIT(mbar, cnt) \
    asm volatile("mbarrier.init.shared.b64 [%0], %1;" :: "r"(mbar), "r"(cnt) : "memory")
#define MBAR_ARRIVE(mbar) \
    asm volatile("mbarrier.arrive.shared.b64 _, [%0];" :: "r"(mbar) : "memory")
#define CPASYNC_MBAR_ARRIVE(mbar) \
    asm volatile("cp.async.mbarrier.arrive.noinc.shared.b64 [%0];" :: "r"(mbar) : "memory")

__device__ __forceinline__ void mbar_wait(uint32_t mbar, uint32_t parity) {
    asm volatile(
        "{\n\t.reg .pred P;\n\t"
        "WL%=:\n\t"
        "mbarrier.try_wait.parity.acquire.cta.shared::cta.b64 P, [%0], %1, 0x989680;\n\t"
        "@P bra WD%=;\n\t"
        "bra WL%=;\n\t"
        "WD%=:\n\t}"
        :: "r"(mbar), "r"(parity) : "memory");
}

// D += A(16x8) * B(8x8), tf32 inputs, fp32 accum.
__device__ __forceinline__ void mma_tf32(float* c, unsigned a0, unsigned a1,
                                         unsigned a2, unsigned a3,
                                         unsigned b0, unsigned b1) {
    asm("mma.sync.aligned.m16n8k8.row.col.f32.tf32.tf32.f32 "
        "{%0,%1,%2,%3}, {%4,%5,%6,%7}, {%8,%9}, {%0,%1,%2,%3};"
        : "+f"(c[0]), "+f"(c[1]), "+f"(c[2]), "+f"(c[3])
        : "r"(a0), "r"(a1), "r"(a2), "r"(a3), "r"(b0), "r"(b1));
}

// =================================================================
// tf32 GEMM, cp.async 3-STAGE ring, ONE __syncthreads per stage.
// Per iter: cp_wait<1> (stage kt landed) -> barrier -> issue(kt+2)
// into the buffer freed by compute(kt-1) -> compute(kt).
// C = A*W^T + bias. M=4096, N=K=768. CVT at fragment load.
// modes: 0 = plain fp32 out; 1 = [h][s][d'] tf32+perm (Q,K);
//        3 = [h][s][d] tf32 plain (V).
// =================================================================
#define GSTR 36
#define GEMM_STAGE (128 * GSTR)                  // words per matrix per stage
#define GEMM_SMEM  (3 * 2 * GEMM_STAGE * 4)      // 110592 bytes

struct GemmPtrs { const float* A; const float* W; const float* bias; float* C; int mode; };
struct GemmArgs3 { GemmPtrs p[3]; };

__global__ __launch_bounds__(256, 2)
void gemm_tf32_kernel(GemmArgs3 args)
{
    extern __shared__ float gsm[];
    const GemmPtrs gp = args.p[blockIdx.z];
    const float* __restrict__ A    = gp.A;
    const float* __restrict__ W    = gp.W;
    const float* __restrict__ bias = gp.bias;
    float* __restrict__ C          = gp.C;
    const int mode = gp.mode;

    const int tid  = threadIdx.x;
    const int warp = tid >> 5;
    const int lane = tid & 31;
    const int gid  = lane >> 2;
    const int tig  = lane & 3;

    const int m0 = blockIdx.y * 128;
    const int n0 = blockIdx.x * 128;
    const int wm = (warp >> 2) * 64;
    const int wn = (warp & 3) * 32;

    const int cr  = tid >> 3;
    const int ccc = (tid & 7) << 2;

    float acc[4][4][4];
#pragma unroll
    for (int mi = 0; mi < 4; ++mi)
#pragma unroll
        for (int ni = 0; ni < 4; ++ni)
#pragma unroll
            for (int f = 0; f < 4; ++f) acc[mi][ni][f] = 0.f;

    auto issue = [&](int kt, int st) {
        float* As = gsm + st * 2 * GEMM_STAGE;
        float* Ws = As + GEMM_STAGE;
        const int k0 = kt * 32;
#pragma unroll
        for (int i = 0; i < 4; ++i) {
            const int r = cr + i * 32;
            cp_async16(As + r * GSTR + ccc, A + (size_t)(m0 + r) * DMODEL + k0 + ccc);
            cp_async16(Ws + r * GSTR + ccc, W + (size_t)(n0 + r) * DMODEL + k0 + ccc);
        }
        cp_commit();
    };

    issue(0, 0);
    issue(1, 1);

    const int NKT = DMODEL / 32;   // 24
    for (int kt = 0; kt < NKT; ++kt) {
        const int buf = kt % 3;
        if (kt + 1 < NKT) cp_wait<1>();   // stage kt complete (kt+1 may pend)
        else              cp_wait<0>();   // last: only kt pending
        __syncthreads();                  // kt visible to all; kt-1 reads done
        if (kt + 2 < NKT) issue(kt + 2, (kt + 2) % 3);

        const float* As = gsm + buf * 2 * GEMM_STAGE;
        const float* Ws = As + GEMM_STAGE;

#pragma unroll
        for (int kk = 0; kk < 4; ++kk) {
            const int k4 = kk * 8;
            unsigned a[4][4], b[4][2];
#pragma unroll
            for (int mi = 0; mi < 4; ++mi) {
                const int r = wm + mi * 16 + gid;
                a[mi][0] = f2tf32(As[r * GSTR + k4 + tig]);
                a[mi][1] = f2tf32(As[(r + 8) * GSTR + k4 + tig]);
                a[mi][2] = f2tf32(As[r * GSTR + k4 + tig + 4]);
                a[mi][3] = f2tf32(As[(r + 8) * GSTR + k4 + tig + 4]);
            }
#pragma unroll
            for (int ni = 0; ni < 4; ++ni) {
                const int n = wn + ni * 8 + gid;
                b[ni][0] = f2tf32(Ws[n * GSTR + k4 + tig]);
                b[ni][1] = f2tf32(Ws[n * GSTR + k4 + tig + 4]);
            }
#pragma unroll
            for (int mi = 0; mi < 4; ++mi)
#pragma unroll
                for (int ni = 0; ni < 4; ++ni)
                    mma_tf32(acc[mi][ni], a[mi][0], a[mi][1], a[mi][2], a[mi][3],
                             b[ni][0], b[ni][1]);
        }
    }

    // epilogue
    const int pt2 = PERM8(2 * tig);
#pragma unroll
    for (int mi = 0; mi < 4; ++mi) {
#pragma unroll
        for (int ni = 0; ni < 4; ++ni) {
            const int n = n0 + wn + ni * 8 + 2 * tig;
            const float b0 = bias[n], b1 = bias[n + 1];
#pragma unroll
            for (int half = 0; half < 2; ++half) {
                const int m = m0 + wm + mi * 16 + gid + half * 8;
                const float v0 = acc[mi][ni][half * 2 + 0] + b0;
                const float v1 = acc[mi][ni][half * 2 + 1] + b1;
                if (mode == 0) {
                    float* dst = C + (size_t)m * DMODEL + n;
                    dst[0] = v0; dst[1] = v1;
                } else if (mode == 1) {
                    const int bse = (n & 63) & ~7;
                    float* dst = C + (size_t)(n >> 6) * (S_LEN * DHEAD)
                                   + (size_t)m * DHEAD + bse;
                    dst[pt2]     = tf32f(v0);
                    dst[pt2 + 2] = tf32f(v1);
                } else {
                    float* dst = C + (size_t)(n >> 6) * (S_LEN * DHEAD)
                                   + (size_t)m * DHEAD + (n & 63);
                    dst[0] = tf32f(v0); dst[1] = tf32f(v1);
                }
            }
        }
    }
}

// =================================================================
// Flash attention (causal), tf32 mma.sync, fixed-shift softmax
// (EXACT R12 version — best measured).
// p = exp2(s*SCL - 16); denominator accumulated per-thread across
// all tiles, reduced once per pass (no running max, no rescale).
// BR=64: 4 compute warps (m16) + 1 producer = 160 threads.
// BC=32, 3-stage K/V ring, no __syncthreads in mainloop.
// CTA i processes q-tiles {63-i, i}: constant 130 tiles per CTA.
// =================================================================
#define FBC    32
#define KSTR   68
#define PSTR   36
#define NSTAGE 3
#define STG_WORDS (2 * FBC * KSTR)                          // 4352 words
#define FL_BAR_OFF ((NSTAGE * STG_WORDS + 64 * PSTR) * 4)   // 61440
#define FLASH_SMEM (FL_BAR_OFF + 16 * NSTAGE)

__global__ __launch_bounds__(160, 3)
void flash_tf32_kernel(const float* __restrict__ Q,
                       const float* __restrict__ K,
                       const float* __restrict__ V,
                       float* __restrict__ O)
{
    extern __shared__ float fsm[];
    float* stages = fsm;                                   // [3][4352]
    unsigned* Ps = (unsigned*)(fsm + NSTAGE * STG_WORDS);  // 64 x 36

    uint32_t sbase;
    asm("{ .reg .u64 t; cvta.to.shared.u64 t, %1; cvt.u32.u64 %0, t; }"
        : "=r"(sbase) : "l"(fsm));
    const uint32_t FULLB  = sbase + FL_BAR_OFF;
    const uint32_t EMPTYB = sbase + FL_BAR_OFF + 8 * NSTAGE;

    const int tid  = threadIdx.x;
    const int warp = tid >> 5;      // 0..3 compute, 4 producer
    const int lane = tid & 31;
    const int gid  = lane >> 2;
    const int tig  = lane & 3;

    const int pairIdx = blockIdx.x;     // 0..31
    const int h       = blockIdx.y;

    const float* Qh = Q + (size_t)h * S_LEN * DHEAD;
    const float* Kh = K + (size_t)h * S_LEN * DHEAD;
    const float* Vh = V + (size_t)h * S_LEN * DHEAD;

    if (tid == 0) {
#pragma unroll
        for (int s = 0; s < NSTAGE; ++s) {
            MBAR_INIT(FULLB + 8 * s, 32);   // cp.async per-lane arrivals
            MBAR_INIT(EMPTYB + 8 * s, 4);   // one arrive per compute warp
        }
    }
    __syncthreads();

    const float SCL   = 0.125f * 1.44269504f;
    const float SHIFT = -16.0f;

    if (warp == 4) {
        // ---------------- producer warp ----------------
        int s = 0;
        unsigned eph = 0;
        int n = 0;
#pragma unroll 1
        for (int pass = 0; pass < 2; ++pass) {
            const int qt = (pass == 0) ? (63 - pairIdx) : pairIdx;
            const int nT = 2 * (qt + 1);
#pragma unroll 1
            for (int t = 0; t < nT; ++t) {
                if (n >= NSTAGE) {
                    mbar_wait(EMPTYB + 8 * s, (eph >> s) & 1);
                    eph ^= 1u << s;
                }
                float* Ks = stages + s * STG_WORDS;
                float* Vs = Ks + FBC * KSTR;
                const int j0 = t * FBC;
                const float* ksrc = Kh + (size_t)(j0 + lane) * DHEAD;
                const float* vsrc = Vh + (size_t)(j0 + lane) * DHEAD;
                float* kdst = Ks + lane * KSTR;
                float* vdst = Vs + lane * KSTR;
#pragma unroll
                for (int c = 0; c < 16; ++c) {
                    cp_async16(kdst + c * 4, ksrc + c * 4);
                    cp_async16(vdst + c * 4, vsrc + c * 4);
                }
                CPASYNC_MBAR_ARRIVE(FULLB + 8 * s);
                if (++s == NSTAGE) s = 0;
                ++n;
            }
        }
        cp_wait<0>();
        return;
    }

    // ---------------- compute warps (m16 each) ----------------
    const int w16 = warp * 16;
    const int r0  = w16 + gid;          // Ps row (0..63)
    const int pos0 = PERM8(2 * tig);

    int s = 0;
    unsigned fph = 0;

#pragma unroll 1
    for (int pass = 0; pass < 2; ++pass) {
        const int qt = (pass == 0) ? (63 - pairIdx) : pairIdx;
        const int m0 = qt * 64;
        const int nT = 2 * (qt + 1);

        // Q fragments (tf32+perm in gmem)
        unsigned qa[8][4];
        {
            const int rr = m0 + w16 + gid;
#pragma unroll
            for (int kk = 0; kk < 8; ++kk) {
                const int c = kk * 8 + 2 * tig;
                uint2 t0 = *(const uint2*)(Qh + (size_t)rr * DHEAD + c);
                uint2 t1 = *(const uint2*)(Qh + (size_t)(rr + 8) * DHEAD + c);
                qa[kk][0] = t0.x; qa[kk][1] = t1.x;
                qa[kk][2] = t0.y; qa[kk][3] = t1.y;
            }
        }

        float o[8][4];
#pragma unroll
        for (int ni = 0; ni < 8; ++ni)
#pragma unroll
            for (int f = 0; f < 4; ++f) o[ni][f] = 0.f;
        float lp0 = 0.f, lp1 = 0.f;     // per-thread denominator partials

#pragma unroll 1
        for (int t = 0; t < nT; ++t) {
            mbar_wait(FULLB + 8 * s, (fph >> s) & 1);
            fph ^= 1u << s;

            const unsigned* Ks = (const unsigned*)(stages + s * STG_WORDS);
            const unsigned* Vs = Ks + FBC * KSTR;
            const int j0 = t * FBC;
            const bool masked = (t >= 2 * qt);

            // ---- S = Q K^T (16 x 32) ----
            float sc[4][4];
#pragma unroll
            for (int ni = 0; ni < 4; ++ni)
#pragma unroll
                for (int f = 0; f < 4; ++f) sc[ni][f] = 0.f;

#pragma unroll
            for (int kk = 0; kk < 8; ++kk) {
                const int kb = kk * 8 + 2 * tig;
#pragma unroll
                for (int ni = 0; ni < 4; ++ni) {
                    const int n = ni * 8 + gid;
                    uint2 bb = *(const uint2*)(Ks + n * KSTR + kb);
                    mma_tf32(sc[ni], qa[kk][0], qa[kk][1], qa[kk][2], qa[kk][3],
                             bb.x, bb.y);
                }
            }

            // ---- fixed-shift scale + causal mask ----
            if (masked) {
                const int q0 = m0 + w16 + gid;
                const int q1 = q0 + 8;
#pragma unroll
                for (int ni = 0; ni < 4; ++ni) {
                    const int kc0 = j0 + ni * 8 + 2 * tig;
                    const int kc1 = kc0 + 1;
                    sc[ni][0] = (kc0 <= q0) ? fmaf(sc[ni][0], SCL, SHIFT) : -1e30f;
                    sc[ni][1] = (kc1 <= q0) ? fmaf(sc[ni][1], SCL, SHIFT) : -1e30f;
                    sc[ni][2] = (kc0 <= q1) ? fmaf(sc[ni][2], SCL, SHIFT) : -1e30f;
                    sc[ni][3] = (kc1 <= q1) ? fmaf(sc[ni][3], SCL, SHIFT) : -1e30f;
                }
            } else {
#pragma unroll
                for (int ni = 0; ni < 4; ++ni)
#pragma unroll
                    for (int f = 0; f < 4; ++f)
                        sc[ni][f] = fmaf(sc[ni][f], SCL, SHIFT);
            }

            // ---- p = exp2(s), accumulate denominator in registers ----
#pragma unroll
            for (int ni = 0; ni < 4; ++ni) {
                const float p0 = exp2f(sc[ni][0]);
                const float p1 = exp2f(sc[ni][1]);
                const float p2 = exp2f(sc[ni][2]);
                const float p3 = exp2f(sc[ni][3]);
                lp0 += p0 + p1; lp1 += p2 + p3;
                const int cb = ni * 8 + pos0;
                Ps[r0 * PSTR + cb]           = f2tf32(p0);
                Ps[r0 * PSTR + cb + 2]       = f2tf32(p1);
                Ps[(r0 + 8) * PSTR + cb]     = f2tf32(p2);
                Ps[(r0 + 8) * PSTR + cb + 2] = f2tf32(p3);
            }

            __syncwarp();   // P stores visible to all lanes of this warp

            // ---- O += P V  (k = 32 keys) ----
#pragma unroll
            for (int kk = 0; kk < 4; ++kk) {
                const int kb = kk * 8 + 2 * tig;
                uint2 alo = *(const uint2*)(Ps + r0 * PSTR + kb);
                uint2 ahi = *(const uint2*)(Ps + (r0 + 8) * PSTR + kb);
#pragma unroll
                for (int ni = 0; ni < 8; ++ni) {
                    const int n = ni * 8 + gid;
                    unsigned b0 = Vs[(kk * 8 + tig) * KSTR + n];
                    unsigned b1 = Vs[(kk * 8 + tig + 4) * KSTR + n];
                    mma_tf32(o[ni], alo.x, ahi.x, alo.y, ahi.y, b0, b1);
                }
            }

            __syncwarp();   // P reads done before next tile overwrites
            if (lane == 0) MBAR_ARRIVE(EMPTYB + 8 * s);
            if (++s == NSTAGE) s = 0;
        }

        // ---- single denominator reduction per pass ----
#pragma unroll
        for (int off = 1; off <= 2; off <<= 1) {
            lp0 += __shfl_xor_sync(0xffffffffu, lp0, off);
            lp1 += __shfl_xor_sync(0xffffffffu, lp1, off);
        }
        const float inv0 = 1.f / lp0;
        const float inv1 = 1.f / lp1;

        // epilogue: normalize + write plain fp32 [s][h*64+d]
        const int rr = m0 + w16 + gid;
#pragma unroll
        for (int ni = 0; ni < 8; ++ni) {
            const int c = h * DHEAD + ni * 8 + 2 * tig;
            float* d0 = O + (size_t)rr * DMODEL + c;
            float* d1 = O + (size_t)(rr + 8) * DMODEL + c;
            d0[0] = o[ni][0] * inv0; d0[1] = o[ni][1] * inv0;
            d1[0] = o[ni][2] * inv1; d1[1] = o[ni][3] * inv1;
        }
    }
}

// =================================================================
extern "C" void kernel_launch(void* const* d_in, const int* in_sizes, int n_in,
                              void* d_out, int out_size)
{
    const float* q  = (const float*)d_in[0];
    const float* k  = (const float*)d_in[1];
    const float* v  = (const float*)d_in[2];
    const float* wq = (const float*)d_in[3];
    const float* bq = (const float*)d_in[4];
    const float* wk = (const float*)d_in[5];
    const float* bk = (const float*)d_in[6];
    const float* wv = (const float*)d_in[7];
    const float* bv = (const float*)d_in[8];
    const float* wo = (const float*)d_in[9];
    const float* bo = (const float*)d_in[10];
    float* out = (float*)d_out;

    void *pq, *pk, *pv, *patt;
    cudaGetSymbolAddress(&pq,  g_qh);
    cudaGetSymbolAddress(&pk,  g_kh);
    cudaGetSymbolAddress(&pv,  g_vh);
    cudaGetSymbolAddress(&patt, g_att);

    static bool attr_done = false;
    if (!attr_done) {
        cudaFuncSetAttribute(gemm_tf32_kernel,
                             cudaFuncAttributeMaxDynamicSharedMemorySize, GEMM_SMEM);
        cudaFuncSetAttribute(flash_tf32_kernel,
                             cudaFuncAttributeMaxDynamicSharedMemorySize, FLASH_SMEM);
        attr_done = true;
    }

    // 1) fused Q/K/V projections (raw fp32 inputs, CVT at fragment load)
    GemmArgs3 qkv;
    qkv.p[0] = { q, wq, bq, (float*)pq, 1 };
    qkv.p[1] = { k, wk, bk, (float*)pk, 1 };
    qkv.p[2] = { v, wv, bv, (float*)pv, 3 };
    gemm_tf32_kernel<<<dim3(DMODEL / 128, S_LEN / 128, 3), 256, GEMM_SMEM>>>(qkv);

    // 2) flash attention (paired q-tiles, fixed-shift softmax — R12 exact)
    flash_tf32_kernel<<<dim3(32, NHEADS), 160, FLASH_SMEM>>>(
        (const float*)pq, (const float*)pk, (const float*)pv, (float*)patt);

    // 3) output projection (raw fp32 g_att, CVT at fragment load)
    GemmArgs3 oproj;
    oproj.p[0] = { (const float*)patt, wo, bo, out, 0 };
    oproj.p[1] = oproj.p[0];
    oproj.p[2] = oproj.p[0];
    gemm_tf32_kernel<<<dim3(DMODEL / 128, S_LEN / 128, 1), 256, GEMM_SMEM>>>(oproj);
}

// round 16
// speedup vs baseline: 1.0938x; 1.0660x over previous
#include <cuda_runtime.h>
#include <cuda_bf16.h>
#include <math.h>
#include <stdint.h>

#define S_LEN   4096
#define DMODEL  768
#define NHEADS  12
#define DHEAD   64

#define PERM8(c) ((((c) & 3) << 1) | ((c) >> 2))

// ---------------- scratch (no allocations allowed) ----------------
__device__ float g_qh[NHEADS * S_LEN * DHEAD];   // [h][s][d']  tf32+perm
__device__ float g_kh[NHEADS * S_LEN * DHEAD];   // [h][s][d']  tf32+perm
__device__ float g_vh[NHEADS * S_LEN * DHEAD];   // [h][s][d]   tf32 plain
__device__ float g_att[S_LEN * DMODEL];          // [s][h*64+d] fp32, atomic-accumulated
__device__ float g_lp[NHEADS * S_LEN];           // softmax denominators (partial sums)

// ---------------- helpers ----------------
__device__ __forceinline__ unsigned f2tf32(float x) {
    unsigned r;
    asm("cvt.rna.tf32.f32 %0, %1;" : "=r"(r) : "f"(x));
    return r;
}
__device__ __forceinline__ float tf32f(float x) {
    return __uint_as_float(f2tf32(x));
}

__device__ __forceinline__ void cp_async16(void* smem, const void* g) {
    unsigned s = (unsigned)__cvta_generic_to_shared(smem);
    asm volatile("cp.async.cg.shared.global [%0], [%1], 16;" :: "r"(s), "l"(g));
}
__device__ __forceinline__ void cp_commit() {
    asm volatile("cp.async.commit_group;");
}
template<int N> __device__ __forceinline__ void cp_wait() {
    asm volatile("cp.async.wait_group %0;" :: "n"(N));
}

#define MBAR_INIT(mbar, cnt) \
    asm volatile("mbarrier.init.shared.b64 [%0], %1;" :: "r"(mbar), "r"(cnt) : "memory")
#define MBAR_ARRIVE(mbar) \
    asm volatile("mbarrier.arrive.shared.b64 _, [%0];" :: "r"(mbar) : "memory")
#define CPASYNC_MBAR_ARRIVE(mbar) \
    asm volatile("cp.async.mbarrier.arrive.noinc.shared.b64 [%0];" :: "r"(mbar) : "memory")

__device__ __forceinline__ void mbar_wait(uint32_t mbar, uint32_t parity) {
    asm volatile(
        "{\n\t.reg .pred P;\n\t"
        "WL%=:\n\t"
        "mbarrier.try_wait.parity.acquire.cta.shared::cta.b64 P, [%0], %1, 0x989680;\n\t"
        "@P bra WD%=;\n\t"
        "bra WL%=;\n\t"
        "WD%=:\n\t}"
        :: "r"(mbar), "r"(parity) : "memory");
}

// D += A(16x8) * B(8x8), tf32 inputs, fp32 accum.
__device__ __forceinline__ void mma_tf32(float* c, unsigned a0, unsigned a1,
                                         unsigned a2, unsigned a3,
                                         unsigned b0, unsigned b1) {
    asm("mma.sync.aligned.m16n8k8.row.col.f32.tf32.tf32.f32 "
        "{%0,%1,%2,%3}, {%4,%5,%6,%7}, {%8,%9}, {%0,%1,%2,%3};"
        : "+f"(c[0]), "+f"(c[1]), "+f"(c[2]), "+f"(c[3])
        : "r"(a0), "r"(a1), "r"(a2), "r"(a3), "r"(b0), "r"(b1));
}

// =================================================================
// zero-fill for the atomic accumulators (g_att + g_lp)
// =================================================================
__global__ __launch_bounds__(256)
void zero_kernel(float* att, float* lp)
{
    const int n_att = S_LEN * DMODEL / 4;        // float4 count
    const int n_lp  = NHEADS * S_LEN / 4;
    const int stride = gridDim.x * 256;
    float4 z = {0.f, 0.f, 0.f, 0.f};
    for (int i = blockIdx.x * 256 + threadIdx.x; i < n_att; i += stride)
        ((float4*)att)[i] = z;
    for (int i = blockIdx.x * 256 + threadIdx.x; i < n_lp; i += stride)
        ((float4*)lp)[i] = z;
}

// =================================================================
// normalize: att[s][c] /= lp[c/64][s]
// =================================================================
__global__ __launch_bounds__(256)
void normalize_kernel(float* att, const float* lp)
{
    const int nq = S_LEN * DMODEL / 4;           // float4 groups; 4 cols share head
    const int stride = gridDim.x * 256;
    for (int i = blockIdx.x * 256 + threadIdx.x; i < nq; i += stride) {
        const int s = i / (DMODEL / 4);
        const int c = (i % (DMODEL / 4)) * 4;
        const float inv = 1.f / lp[(c >> 6) * S_LEN + s];
        float4 v = ((float4*)att)[i];
        v.x *= inv; v.y *= inv; v.z *= inv; v.w *= inv;
        ((float4*)att)[i] = v;
    }
}

// =================================================================
// tf32 GEMM (EXACT R12 version): cp.async 2-stage, CVT at fragment
// load. C = A*W^T + bias. M=4096, N=K=768.
// modes: 0 = plain fp32 out; 1 = [h][s][d'] tf32+perm (Q,K);
//        3 = [h][s][d] tf32 plain (V).
// =================================================================
#define GSTR 36
#define GEMM_STAGE (128 * GSTR)
#define GEMM_SMEM  (2 * 2 * GEMM_STAGE * 4)      // 73728 bytes

struct GemmPtrs { const float* A; const float* W; const float* bias; float* C; int mode; };
struct GemmArgs3 { GemmPtrs p[3]; };

__global__ __launch_bounds__(256, 2)
void gemm_tf32_kernel(GemmArgs3 args)
{
    extern __shared__ float gsm[];
    const GemmPtrs gp = args.p[blockIdx.z];
    const float* __restrict__ A    = gp.A;
    const float* __restrict__ W    = gp.W;
    const float* __restrict__ bias = gp.bias;
    float* __restrict__ C          = gp.C;
    const int mode = gp.mode;

    const int tid  = threadIdx.x;
    const int warp = tid >> 5;
    const int lane = tid & 31;
    const int gid  = lane >> 2;
    const int tig  = lane & 3;

    const int m0 = blockIdx.y * 128;
    const int n0 = blockIdx.x * 128;
    const int wm = (warp >> 2) * 64;
    const int wn = (warp & 3) * 32;

    const int cr  = tid >> 3;
    const int ccc = (tid & 7) << 2;

    float acc[4][4][4];
#pragma unroll
    for (int mi = 0; mi < 4; ++mi)
#pragma unroll
        for (int ni = 0; ni < 4; ++ni)
#pragma unroll
            for (int f = 0; f < 4; ++f) acc[mi][ni][f] = 0.f;

    auto issue = [&](int kt, int st) {
        float* As = gsm + st * 2 * GEMM_STAGE;
        float* Ws = As + GEMM_STAGE;
        const int k0 = kt * 32;
#pragma unroll
        for (int i = 0; i < 4; ++i) {
            const int r = cr + i * 32;
            cp_async16(As + r * GSTR + ccc, A + (size_t)(m0 + r) * DMODEL + k0 + ccc);
            cp_async16(Ws + r * GSTR + ccc, W + (size_t)(n0 + r) * DMODEL + k0 + ccc);
        }
        cp_commit();
    };

    issue(0, 0);

    const int NKT = DMODEL / 32;   // 24
    for (int kt = 0; kt < NKT; ++kt) {
        const int buf = kt & 1;
        if (kt + 1 < NKT) { issue(kt + 1, buf ^ 1); cp_wait<1>(); }
        else              { cp_wait<0>(); }
        __syncthreads();

        const float* As = gsm + buf * 2 * GEMM_STAGE;
        const float* Ws = As + GEMM_STAGE;

#pragma unroll
        for (int kk = 0; kk < 4; ++kk) {
            const int k4 = kk * 8;
            unsigned a[4][4], b[4][2];
#pragma unroll
            for (int mi = 0; mi < 4; ++mi) {
                const int r = wm + mi * 16 + gid;
                a[mi][0] = f2tf32(As[r * GSTR + k4 + tig]);
                a[mi][1] = f2tf32(As[(r + 8) * GSTR + k4 + tig]);
                a[mi][2] = f2tf32(As[r * GSTR + k4 + tig + 4]);
                a[mi][3] = f2tf32(As[(r + 8) * GSTR + k4 + tig + 4]);
            }
#pragma unroll
            for (int ni = 0; ni < 4; ++ni) {
                const int n = wn + ni * 8 + gid;
                b[ni][0] = f2tf32(Ws[n * GSTR + k4 + tig]);
                b[ni][1] = f2tf32(Ws[n * GSTR + k4 + tig + 4]);
            }
#pragma unroll
            for (int mi = 0; mi < 4; ++mi)
#pragma unroll
                for (int ni = 0; ni < 4; ++ni)
                    mma_tf32(acc[mi][ni], a[mi][0], a[mi][1], a[mi][2], a[mi][3],
                             b[ni][0], b[ni][1]);
        }
        __syncthreads();
    }

    // epilogue
    const int pt2 = PERM8(2 * tig);
#pragma unroll
    for (int mi = 0; mi < 4; ++mi) {
#pragma unroll
        for (int ni = 0; ni < 4; ++ni) {
            const int n = n0 + wn + ni * 8 + 2 * tig;
            const float b0 = bias[n], b1 = bias[n + 1];
#pragma unroll
            for (int half = 0; half < 2; ++half) {
                const int m = m0 + wm + mi * 16 + gid + half * 8;
                const float v0 = acc[mi][ni][half * 2 + 0] + b0;
                const float v1 = acc[mi][ni][half * 2 + 1] + b1;
                if (mode == 0) {
                    float* dst = C + (size_t)m * DMODEL + n;
                    dst[0] = v0; dst[1] = v1;
                } else if (mode == 1) {
                    const int bse = (n & 63) & ~7;
                    float* dst = C + (size_t)(n >> 6) * (S_LEN * DHEAD)
                                   + (size_t)m * DHEAD + bse;
                    dst[pt2]     = tf32f(v0);
                    dst[pt2 + 2] = tf32f(v1);
                } else {
                    float* dst = C + (size_t)(n >> 6) * (S_LEN * DHEAD)
                                   + (size_t)m * DHEAD + (n & 63);
                    dst[0] = tf32f(v0); dst[1] = tf32f(v1);
                }
            }
        }
    }
}

// =================================================================
// Flash attention (causal), tf32 mma.sync, fixed-shift softmax.
// GLOBAL CHUNKED WORK PARTITION: the 49920 BC-32 tiles (all heads,
// all q-tiles) are split into 444 equal contiguous chunks, one per
// CTA. Fixed-shift softmax is additive over disjoint key sets, so
// chunks crossing (head,q-tile) boundaries just atomicAdd partial
// unnormalized O and partial lp. Per-tile body EXACTLY R12.
// BR=64: 4 compute warps (m16) + 1 producer = 160 threads.
// =================================================================
#define FBC    32
#define KSTR   68
#define PSTR   36
#define NSTAGE 3
#define STG_WORDS (2 * FBC * KSTR)                          // 4352 words
#define FL_BAR_OFF ((NSTAGE * STG_WORDS + 64 * PSTR) * 4)   // 61440
#define FLASH_SMEM (FL_BAR_OFF + 16 * NSTAGE)
#define N_CHUNK 444
#define TOT_TILES (NHEADS * 64 * 65)                        // 49920
#define HEAD_TILES (64 * 65)                                // 4160

__device__ __forceinline__ void decode_g(int g, int& h, int& q, int& t) {
    h = g / HEAD_TILES;
    const int r = g - h * HEAD_TILES;
    q = (int)((sqrtf(4.0f * (float)r + 1.0f) - 1.0f) * 0.5f);
    while ((q + 1) * (q + 2) <= r) ++q;
    while (q * (q + 1) > r) --q;
    t = r - q * (q + 1);
}

__global__ __launch_bounds__(160, 3)
void flash_tf32_kernel(const float* __restrict__ Q,
                       const float* __restrict__ K,
                       const float* __restrict__ V,
                       float* __restrict__ O,
                       float* __restrict__ LP)
{
    extern __shared__ float fsm[];
    float* stages = fsm;                                   // [3][4352]
    unsigned* Ps = (unsigned*)(fsm + NSTAGE * STG_WORDS);  // 64 x 36

    uint32_t sbase;
    asm("{ .reg .u64 t; cvta.to.shared.u64 t, %1; cvt.u32.u64 %0, t; }"
        : "=r"(sbase) : "l"(fsm));
    const uint32_t FULLB  = sbase + FL_BAR_OFF;
    const uint32_t EMPTYB = sbase + FL_BAR_OFF + 8 * NSTAGE;

    const int tid  = threadIdx.x;
    const int warp = tid >> 5;      // 0..3 compute, 4 producer
    const int lane = tid & 31;
    const int gid  = lane >> 2;
    const int tig  = lane & 3;

    const int cta = blockIdx.x;     // 0..443
    const int g0 = (int)(((long long)cta * TOT_TILES) / N_CHUNK);
    const int g1 = (int)(((long long)(cta + 1) * TOT_TILES) / N_CHUNK);

    if (tid == 0) {
#pragma unroll
        for (int s = 0; s < NSTAGE; ++s) {
            MBAR_INIT(FULLB + 8 * s, 32);   // cp.async per-lane arrivals
            MBAR_INIT(EMPTYB + 8 * s, 4);   // one arrive per compute warp
        }
    }
    __syncthreads();

    const float SCL   = 0.125f * 1.44269504f;
    const float SHIFT = -16.0f;

    if (warp == 4) {
        // ---------------- producer warp ----------------
        int s = 0;
        unsigned eph = 0;
        int n = 0;
        int g = g0;
#pragma unroll 1
        while (g < g1) {
            int h, q, t0;
            decode_g(g, h, q, t0);
            const int segEnd = 2 * (q + 1);
            int run = segEnd - t0;
            if (run > g1 - g) run = g1 - g;
            const float* Kh = K + (size_t)h * S_LEN * DHEAD;
            const float* Vh = V + (size_t)h * S_LEN * DHEAD;
#pragma unroll 1
            for (int i = 0; i < run; ++i) {
                if (n >= NSTAGE) {
                    mbar_wait(EMPTYB + 8 * s, (eph >> s) & 1);
                    eph ^= 1u << s;
                }
                float* Ks = stages + s * STG_WORDS;
                float* Vs = Ks + FBC * KSTR;
                const int j0 = (t0 + i) * FBC;
                const float* ksrc = Kh + (size_t)(j0 + lane) * DHEAD;
                const float* vsrc = Vh + (size_t)(j0 + lane) * DHEAD;
                float* kdst = Ks + lane * KSTR;
                float* vdst = Vs + lane * KSTR;
#pragma unroll
                for (int c = 0; c < 16; ++c) {
                    cp_async16(kdst + c * 4, ksrc + c * 4);
                    cp_async16(vdst + c * 4, vsrc + c * 4);
                }
                CPASYNC_MBAR_ARRIVE(FULLB + 8 * s);
                if (++s == NSTAGE) s = 0;
                ++n;
            }
            g += run;
        }
        cp_wait<0>();
        return;
    }

    // ---------------- compute warps (m16 each) ----------------
    const int w16 = warp * 16;
    const int r0  = w16 + gid;          // Ps row (0..63)
    const int pos0 = PERM8(2 * tig);

    int s = 0;
    unsigned fph = 0;
    int g = g0;

#pragma unroll 1
    while (g < g1) {
        int h, q, t0;
        decode_g(g, h, q, t0);
        const int segEnd = 2 * (q + 1);
        int run = segEnd - t0;
        if (run > g1 - g) run = g1 - g;

        const int m0 = q * 64;
        const float* Qh = Q + (size_t)h * S_LEN * DHEAD;

        // Q fragments (tf32+perm in gmem)
        unsigned qa[8][4];
        {
            const int rr = m0 + w16 + gid;
#pragma unroll
            for (int kk = 0; kk < 8; ++kk) {
                const int c = kk * 8 + 2 * tig;
                uint2 t0v = *(const uint2*)(Qh + (size_t)rr * DHEAD + c);
                uint2 t1v = *(const uint2*)(Qh + (size_t)(rr + 8) * DHEAD + c);
                qa[kk][0] = t0v.x; qa[kk][1] = t1v.x;
                qa[kk][2] = t0v.y; qa[kk][3] = t1v.y;
            }
        }

        float o[8][4];
#pragma unroll
        for (int ni = 0; ni < 8; ++ni)
#pragma unroll
            for (int f = 0; f < 4; ++f) o[ni][f] = 0.f;
        float lp0 = 0.f, lp1 = 0.f;

#pragma unroll 1
        for (int i = 0; i < run; ++i) {
            const int t = t0 + i;
            mbar_wait(FULLB + 8 * s, (fph >> s) & 1);
            fph ^= 1u << s;

            const unsigned* Ks = (const unsigned*)(stages + s * STG_WORDS);
            const unsigned* Vs = Ks + FBC * KSTR;
            const int j0 = t * FBC;
            const bool masked = (t >= 2 * q);

            // ---- S = Q K^T (16 x 32) ----
            float sc[4][4];
#pragma unroll
            for (int ni = 0; ni < 4; ++ni)
#pragma unroll
                for (int f = 0; f < 4; ++f) sc[ni][f] = 0.f;

#pragma unroll
            for (int kk = 0; kk < 8; ++kk) {
                const int kb = kk * 8 + 2 * tig;
#pragma unroll
                for (int ni = 0; ni < 4; ++ni) {
                    const int n = ni * 8 + gid;
                    uint2 bb = *(const uint2*)(Ks + n * KSTR + kb);
                    mma_tf32(sc[ni], qa[kk][0], qa[kk][1], qa[kk][2], qa[kk][3],
                             bb.x, bb.y);
                }
            }

            // ---- fixed-shift scale + causal mask ----
            if (masked) {
                const int q0 = m0 + w16 + gid;
                const int q1r = q0 + 8;
#pragma unroll
                for (int ni = 0; ni < 4; ++ni) {
                    const int kc0 = j0 + ni * 8 + 2 * tig;
                    const int kc1 = kc0 + 1;
                    sc[ni][0] = (kc0 <= q0)  ? fmaf(sc[ni][0], SCL, SHIFT) : -1e30f;
                    sc[ni][1] = (kc1 <= q0)  ? fmaf(sc[ni][1], SCL, SHIFT) : -1e30f;
                    sc[ni][2] = (kc0 <= q1r) ? fmaf(sc[ni][2], SCL, SHIFT) : -1e30f;
                    sc[ni][3] = (kc1 <= q1r) ? fmaf(sc[ni][3], SCL, SHIFT) : -1e30f;
                }
            } else {
#pragma unroll
                for (int ni = 0; ni < 4; ++ni)
#pragma unroll
                    for (int f = 0; f < 4; ++f)
                        sc[ni][f] = fmaf(sc[ni][f], SCL, SHIFT);
            }

            // ---- p = exp2(s), accumulate denominator in registers ----
#pragma unroll
            for (int ni = 0; ni < 4; ++ni) {
                const float p0 = exp2f(sc[ni][0]);
                const float p1 = exp2f(sc[ni][1]);
                const float p2 = exp2f(sc[ni][2]);
                const float p3 = exp2f(sc[ni][3]);
                lp0 += p0 + p1; lp1 += p2 + p3;
                const int cb = ni * 8 + pos0;
                Ps[r0 * PSTR + cb]           = f2tf32(p0);
                Ps[r0 * PSTR + cb + 2]       = f2tf32(p1);
                Ps[(r0 + 8) * PSTR + cb]     = f2tf32(p2);
                Ps[(r0 + 8) * PSTR + cb + 2] = f2tf32(p3);
            }

            __syncwarp();   // P stores visible to all lanes of this warp

            // ---- O += P V  (k = 32 keys) ----
#pragma unroll
            for (int kk = 0; kk < 4; ++kk) {
                const int kb = kk * 8 + 2 * tig;
                uint2 alo = *(const uint2*)(Ps + r0 * PSTR + kb);
                uint2 ahi = *(const uint2*)(Ps + (r0 + 8) * PSTR + kb);
#pragma unroll
                for (int ni = 0; ni < 8; ++ni) {
                    const int n = ni * 8 + gid;
                    unsigned b0 = Vs[(kk * 8 + tig) * KSTR + n];
                    unsigned b1 = Vs[(kk * 8 + tig + 4) * KSTR + n];
                    mma_tf32(o[ni], alo.x, ahi.x, alo.y, ahi.y, b0, b1);
                }
            }

            __syncwarp();   // P reads done before next tile overwrites
            if (lane == 0) MBAR_ARRIVE(EMPTYB + 8 * s);
            if (++s == NSTAGE) s = 0;
        }

        // ---- segment epilogue: atomic partial sums ----
#pragma unroll
        for (int off = 1; off <= 2; off <<= 1) {
            lp0 += __shfl_xor_sync(0xffffffffu, lp0, off);
            lp1 += __shfl_xor_sync(0xffffffffu, lp1, off);
        }
        const int rr = m0 + w16 + gid;
        if (tig == 0) {
            atomicAdd(&LP[h * S_LEN + rr],     lp0);
            atomicAdd(&LP[h * S_LEN + rr + 8], lp1);
        }
#pragma unroll
        for (int ni = 0; ni < 8; ++ni) {
            const int c = h * DHEAD + ni * 8 + 2 * tig;
            atomicAdd(&O[(size_t)rr * DMODEL + c],           o[ni][0]);
            atomicAdd(&O[(size_t)rr * DMODEL + c + 1],       o[ni][1]);
            atomicAdd(&O[(size_t)(rr + 8) * DMODEL + c],     o[ni][2]);
            atomicAdd(&O[(size_t)(rr + 8) * DMODEL + c + 1], o[ni][3]);
        }

        g += run;
    }
}

// =================================================================
extern "C" void kernel_launch(void* const* d_in, const int* in_sizes, int n_in,
                              void* d_out, int out_size)
{
    const float* q  = (const float*)d_in[0];
    const float* k  = (const float*)d_in[1];
    const float* v  = (const float*)d_in[2];
    const float* wq = (const float*)d_in[3];
    const float* bq = (const float*)d_in[4];
    const float* wk = (const float*)d_in[5];
    const float* bk = (const float*)d_in[6];
    const float* wv = (const float*)d_in[7];
    const float* bv = (const float*)d_in[8];
    const float* wo = (const float*)d_in[9];
    const float* bo = (const float*)d_in[10];
    float* out = (float*)d_out;

    void *pq, *pk, *pv, *patt, *plp;
    cudaGetSymbolAddress(&pq,  g_qh);
    cudaGetSymbolAddress(&pk,  g_kh);
    cudaGetSymbolAddress(&pv,  g_vh);
    cudaGetSymbolAddress(&patt, g_att);
    cudaGetSymbolAddress(&plp,  g_lp);

    static bool attr_done = false;
    if (!attr_done) {
        cudaFuncSetAttribute(gemm_tf32_kernel,
                             cudaFuncAttributeMaxDynamicSharedMemorySize, GEMM_SMEM);
        cudaFuncSetAttribute(flash_tf32_kernel,
                             cudaFuncAttributeMaxDynamicSharedMemorySize, FLASH_SMEM);
        attr_done = true;
    }

    // 0) zero the atomic accumulators
    zero_kernel<<<592, 256>>>((float*)patt, (float*)plp);

    // 1) fused Q/K/V projections (raw fp32 inputs, CVT at fragment load)
    GemmArgs3 qkv;
    qkv.p[0] = { q, wq, bq, (float*)pq, 1 };
    qkv.p[1] = { k, wk, bk, (float*)pk, 1 };
    qkv.p[2] = { v, wv, bv, (float*)pv, 3 };
    gemm_tf32_kernel<<<dim3(DMODEL / 128, S_LEN / 128, 3), 256, GEMM_SMEM>>>(qkv);

    // 2) flash attention: 444 equal global chunks, atomic partial sums
    flash_tf32_kernel<<<N_CHUNK, 160, FLASH_SMEM>>>(
        (const float*)pq, (const float*)pk, (const float*)pv,
        (float*)patt, (float*)plp);

    // 3) normalize accumulated attention output
    normalize_kernel<<<1184, 256>>>((float*)patt, (const float*)plp);

    // 4) output projection (raw fp32 g_att, CVT at fragment load)
    GemmArgs3 oproj;
    oproj.p[0] = { (const float*)patt, wo, bo, out, 0 };
    oproj.p[1] = oproj.p[0];
    oproj.p[2] = oproj.p[0];
    gemm_tf32_kernel<<<dim3(DMODEL / 128, S_LEN / 128, 1), 256, GEMM_SMEM>>>(oproj);
}